// round 16
// baseline (speedup 1.0000x reference)
#include <cuda_runtime.h>
#include <cuda_fp16.h>
#include <cstdint>

// ---------------------------------------------------------------------------
// Problem dims (fixed)
// ---------------------------------------------------------------------------
#define Bd 8
#define Sd 2048
#define Id 1024
#define Hd 4096
#define Od 1024
#define M_TOT (Bd * Sd)          // 16384
#define M_HALF (M_TOT / 2)       // 8192 (L2-resident hidden slice)

#define NCHUNK 64
#define CHUNK  32                // NCHUNK*CHUNK == Sd
#define NCH    (Bd * Id)         // 8192 channels
#define NPAIR  (NCH / 2)         // 4096 channel-pairs
#define TBATCH 8                 // timesteps batched per load group
#define RPAIRS 8                 // pairs per recurrence block

// ---------------------------------------------------------------------------
// Scratch (__device__ globals, allocation-free)
// ---------------------------------------------------------------------------
__device__ __half g_xh[(size_t)M_TOT * Id];        // 32 MB
__device__ __half g_Wgh[(size_t)Id * Id];          //  2 MB
__device__ __half g_W1h[(size_t)Hd * Id];          //  8 MB
__device__ __half g_W2h[(size_t)Od * Hd];          //  8 MB
__device__ __half g_decayh[(size_t)M_TOT * Id];    // 32 MB (fp16 decay)
__device__ __half g_comb[(size_t)M_TOT * Id];      // 32 MB
__device__ __half g_hidden[(size_t)M_TOT * Hd];    // 128 MB
__device__ float2 g_P2[NCHUNK * NPAIR];            // kept for ABI stability (unused)
__device__ float2 g_Q2[NCHUNK * NPAIR];

// ---------------------------------------------------------------------------
// PTX helpers
// ---------------------------------------------------------------------------
__device__ __forceinline__ uint32_t smem_u32(const void* p) {
    uint32_t a;
    asm("{ .reg .u64 t; cvta.to.shared.u64 t, %1; cvt.u32.u64 %0, t; }"
        : "=r"(a) : "l"(p));
    return a;
}

#define CP_ASYNC16(dst, src) \
    asm volatile("cp.async.cg.shared.global [%0], [%1], 16;" :: "r"(dst), "l"(src))
#define CP_COMMIT() asm volatile("cp.async.commit_group;" ::: "memory")
#define CP_WAIT(n)  asm volatile("cp.async.wait_group %0;" :: "n"(n) : "memory")

#define LDSM_X4(r0, r1, r2, r3, addr)                                        \
    asm volatile("ldmatrix.sync.aligned.m8n8.x4.shared.b16 {%0,%1,%2,%3}, [%4];" \
        : "=r"(r0), "=r"(r1), "=r"(r2), "=r"(r3) : "r"(addr))

__device__ __forceinline__ void mma16(float c[4], const uint32_t a[4], const uint32_t b[2]) {
    asm volatile(
        "mma.sync.aligned.m16n8k16.row.col.f32.f16.f16.f32 "
        "{%0,%1,%2,%3}, {%4,%5,%6,%7}, {%8,%9}, {%0,%1,%2,%3};"
        : "+f"(c[0]), "+f"(c[1]), "+f"(c[2]), "+f"(c[3])
        : "r"(a[0]), "r"(a[1]), "r"(a[2]), "r"(a[3]), "r"(b[0]), "r"(b[1]));
}

// ---------------------------------------------------------------------------
// fp16 GEMM: CTA 128x128, 4 warps 64x64, K-slab 64, 2-stage cp.async,
// fragment double-buffering, early buffer handoff. (unchanged)
// EPI: 0 = none (f32 out), 1 = relu (f16 out), 2 = sigmoid (f16 out)
// ---------------------------------------------------------------------------
#define KSLAB 64
#define ATILE 16384                   // 128 rows * 128 B
#define STAGE (2 * ATILE)             // A + B = 32 KB
#define DYN_SMEM (2 * STAGE)          // 64 KB

__device__ __forceinline__ void fill_slab(uint32_t sbuf, const __half* ga,
                                          const __half* gb, int K, int k0, int tid) {
    const int r0 = tid >> 3;          // 0..15
    const int c  = tid & 7;           // 16B chunk within 128B row
#pragma unroll
    for (int q = 0; q < 8; q++) {
        const int row = r0 + q * 16;
        const uint32_t sw = (uint32_t)((c ^ (row & 7)) << 4);
        CP_ASYNC16(sbuf + row * 128 + sw, ga + (size_t)row * K + k0 + c * 8);
    }
#pragma unroll
    for (int q = 0; q < 8; q++) {
        const int row = r0 + q * 16;
        const uint32_t sw = (uint32_t)((c ^ (row & 7)) << 4);
        CP_ASYNC16(sbuf + ATILE + row * 128 + sw, gb + (size_t)row * K + k0 + c * 8);
    }
}

struct FragCoords {
    int rA, cA, xA, rB, cB, xB;
};

__device__ __forceinline__ void load_frags(uint32_t buf, int kk,
                                           uint32_t af[4][4], uint32_t bf[8][2],
                                           const FragCoords& fc) {
#pragma unroll
    for (int mt = 0; mt < 4; mt++) {
        const uint32_t addr = buf + (fc.rA + mt * 16) * 128 +
                              (uint32_t)(((kk * 2 + fc.cA) ^ fc.xA) << 4);
        LDSM_X4(af[mt][0], af[mt][1], af[mt][2], af[mt][3], addr);
    }
#pragma unroll
    for (int p = 0; p < 4; p++) {
        const uint32_t addr = buf + ATILE + (fc.rB + p * 16) * 128 +
                              (uint32_t)(((kk * 2 + fc.cB) ^ fc.xB) << 4);
        LDSM_X4(bf[2 * p][0], bf[2 * p][1], bf[2 * p + 1][0], bf[2 * p + 1][1], addr);
    }
}

template <int EPI>
__global__ void __launch_bounds__(128, 2)
gemm_h(const __half* __restrict__ A, const __half* __restrict__ Bm,
       const float* __restrict__ bias, void* __restrict__ Cout,
       int M, int N, int K) {
    extern __shared__ char smem[];
    const uint32_t sb = smem_u32(smem);

    const int tid  = threadIdx.x;
    const int lane = tid & 31;
    const int warp = tid >> 5;
    const int g    = lane >> 2;
    const int tig  = lane & 3;
    const int wm   = (warp >> 1) * 64;
    const int wn   = (warp & 1) * 64;

    FragCoords fc;
    fc.rA = wm + (lane & 15);
    fc.cA = lane >> 4;
    fc.xA = fc.rA & 7;
    fc.rB = wn + (lane & 7) + ((lane >> 4) << 3);
    fc.cB = (lane >> 3) & 1;
    fc.xB = fc.rB & 7;

    const size_t blockM = (size_t)blockIdx.y * 128;
    const size_t blockN = (size_t)blockIdx.x * 128;
    const __half* ga = A  + blockM * (size_t)K;
    const __half* gb = Bm + blockN * (size_t)K;

    float c[4][8][4] = {};

    const int nk = K / KSLAB;
    fill_slab(sb,         ga, gb, K, 0,     tid); CP_COMMIT();
    fill_slab(sb + STAGE, ga, gb, K, KSLAB, tid); CP_COMMIT();

    for (int kt = 0; kt < nk; kt++) {
        CP_WAIT(1);
        __syncthreads();

        const uint32_t buf = sb + (kt & 1) * STAGE;
        uint32_t af[2][4][4], bf[2][8][2];
        load_frags(buf, 0, af[0], bf[0], fc);

#pragma unroll
        for (int kk = 0; kk < 4; kk++) {
            const int cur = kk & 1;
            if (kk < 3) {
                load_frags(buf, kk + 1, af[cur ^ 1], bf[cur ^ 1], fc);
            } else {
                __syncthreads();
                if (kt + 2 < nk)
                    fill_slab(buf, ga, gb, K, (kt + 2) * KSLAB, tid);
                CP_COMMIT();
            }
#pragma unroll
            for (int mt = 0; mt < 4; mt++)
#pragma unroll
                for (int nt = 0; nt < 8; nt++)
                    mma16(c[mt][nt], af[cur][mt], bf[cur][nt]);
        }
    }

    // ---- epilogue ----
#pragma unroll
    for (int mt = 0; mt < 4; mt++) {
#pragma unroll
        for (int nt = 0; nt < 8; nt++) {
            const size_t row = blockM + wm + mt * 16 + g;
            const size_t col = blockN + wn + nt * 8 + 2 * tig;
            const float bv0 = __ldg(bias + col);
            const float bv1 = __ldg(bias + col + 1);
            float v00 = c[mt][nt][0] + bv0, v01 = c[mt][nt][1] + bv1;
            float v10 = c[mt][nt][2] + bv0, v11 = c[mt][nt][3] + bv1;
            if (EPI == 1 || EPI == 2) {
                if (EPI == 1) {
                    v00 = v00 > 0.f ? v00 : 0.f;  v01 = v01 > 0.f ? v01 : 0.f;
                    v10 = v10 > 0.f ? v10 : 0.f;  v11 = v11 > 0.f ? v11 : 0.f;
                } else {
                    v00 = 1.f / (1.f + __expf(-v00)); v01 = 1.f / (1.f + __expf(-v01));
                    v10 = 1.f / (1.f + __expf(-v10)); v11 = 1.f / (1.f + __expf(-v11));
                }
                __half* Ch = (__half*)Cout;
                *reinterpret_cast<__half2*>(&Ch[row * N + col]) =
                    __floats2half2_rn(v00, v01);
                *reinterpret_cast<__half2*>(&Ch[(row + 8) * N + col]) =
                    __floats2half2_rn(v10, v11);
            } else {
                float* Cf = (float*)Cout;
                *reinterpret_cast<float2*>(&Cf[row * N + col]) = make_float2(v00, v01);
                *reinterpret_cast<float2*>(&Cf[(row + 8) * N + col]) = make_float2(v10, v11);
            }
        }
    }
}

// ---------------------------------------------------------------------------
// Merged fp32 -> fp16 conversion (single launch; clock canary ~11-13us fast)
// ---------------------------------------------------------------------------
#define F2H_N4_X  4194304
#define F2H_N4_W1 1048576
#define F2H_N4_W2 1048576
#define F2H_N4_WG 262144
#define F2H_TOTAL (F2H_N4_X + F2H_N4_W1 + F2H_N4_W2 + F2H_N4_WG)

__global__ void f2hall(const float* __restrict__ x,  const float* __restrict__ W1,
                       const float* __restrict__ W2, const float* __restrict__ Wg,
                       __half* __restrict__ xh,  __half* __restrict__ W1h,
                       __half* __restrict__ W2h, __half* __restrict__ Wgh) {
    int i = blockIdx.x * blockDim.x + threadIdx.x;
    const float* src;
    __half* dst;
    if (i < F2H_N4_X)                      { src = x;  dst = xh; }
    else if (i < F2H_N4_X + F2H_N4_W1)     { src = W1; dst = W1h; i -= F2H_N4_X; }
    else if (i < F2H_N4_X + F2H_N4_W1 + F2H_N4_W2)
                                           { src = W2; dst = W2h; i -= F2H_N4_X + F2H_N4_W1; }
    else                                   { src = Wg; dst = Wgh; i -= F2H_N4_X + F2H_N4_W1 + F2H_N4_W2; }
    float4 v = reinterpret_cast<const float4*>(src)[i];
    __half2 h0 = __floats2half2_rn(v.x, v.y);
    __half2 h1 = __floats2half2_rn(v.z, v.w);
    uint2 u;
    u.x = *reinterpret_cast<uint32_t*>(&h0);
    u.y = *reinterpret_cast<uint32_t*>(&h1);
    reinterpret_cast<uint2*>(dst)[i] = u;
}

// ---------------------------------------------------------------------------
// Fused recurrence: one kernel. Block = 512 threads = RPAIRS(8) pairs x 64
// chunks. Phase 1 computes per-chunk (P,Q) summaries into smem; block scan
// folds prefixes; phase 2 re-walks the chunk (L2-resident) and emits comb.
// Arithmetic order identical to the previous two-pass version.
// ---------------------------------------------------------------------------
__global__ void __launch_bounds__(512, 2)
recur_fused(const __half* __restrict__ xh) {
    __shared__ float4 sPQ[NCHUNK][RPAIRS];   // (Px,Py,Qx,Qy)

    const int t     = threadIdx.x;
    const int pl    = t & (RPAIRS - 1);          // pair within block
    const int chunk = t >> 3;                    // 0..63
    const int pr    = blockIdx.x * RPAIRS + pl;  // global pair
    const int b     = pr >> 9;                   // / (Id/2)
    const int i     = (pr & 511) << 1;           // channel
    const size_t base = (size_t)b * Sd * Id + (size_t)chunk * CHUNK * Id + i;

    // ---- phase 1: per-chunk summary ----
    float Px = 1.f, Py = 1.f, Qx = 0.f, Qy = 0.f;
#pragma unroll
    for (int t0 = 0; t0 < CHUNK; t0 += TBATCH) {
        float2 d[TBATCH];
        float2 xv[TBATCH];
#pragma unroll
        for (int j = 0; j < TBATCH; j++) {
            d[j]  = __half22float2(*reinterpret_cast<const __half2*>(
                g_decayh + base + (size_t)(t0 + j) * Id));
            xv[j] = __half22float2(*reinterpret_cast<const __half2*>(
                xh + base + (size_t)(t0 + j) * Id));
        }
#pragma unroll
        for (int j = 0; j < TBATCH; j++) {
            Px *= d[j].x;                        Py *= d[j].y;
            Qx = Qx * d[j].x + (1.f - d[j].x) * xv[j].x;
            Qy = Qy * d[j].y + (1.f - d[j].y) * xv[j].y;
        }
    }
    sPQ[chunk][pl] = make_float4(Px, Py, Qx, Qy);
    __syncthreads();

    // ---- prefix fold over earlier chunks ----
    float bx = 0.f, by = 0.f;
    for (int j = 0; j < chunk; j++) {
        const float4 pq = sPQ[j][pl];
        bx = pq.x * bx + pq.z;
        by = pq.y * by + pq.w;
    }

    // ---- phase 2: emit combined (re-read hits L2) ----
#pragma unroll
    for (int t0 = 0; t0 < CHUNK; t0 += TBATCH) {
        float2 d[TBATCH];
        float2 xv[TBATCH];
#pragma unroll
        for (int j = 0; j < TBATCH; j++) {
            d[j]  = __half22float2(*reinterpret_cast<const __half2*>(
                g_decayh + base + (size_t)(t0 + j) * Id));
            xv[j] = __half22float2(*reinterpret_cast<const __half2*>(
                xh + base + (size_t)(t0 + j) * Id));
        }
#pragma unroll
        for (int j = 0; j < TBATCH; j++) {
            bx = bx * d[j].x + (1.f - d[j].x) * xv[j].x;
            by = by * d[j].y + (1.f - d[j].y) * xv[j].y;
            *reinterpret_cast<__half2*>(g_comb + base + (size_t)(t0 + j) * Id) =
                __floats2half2_rn(xv[j].x * d[j].x + bx, xv[j].y * d[j].y + by);
        }
    }
}

// ---------------------------------------------------------------------------
// Launch: f2h, gemm1, recur_fused, then M-sliced MLP so each hidden slice
// (64 MB) stays L2-resident between its gemm2 and gemm3.
// ---------------------------------------------------------------------------
extern "C" void kernel_launch(void* const* d_in, const int* in_sizes, int n_in,
                              void* d_out, int out_size) {
    const float* x  = (const float*)d_in[0];
    const float* W1 = (const float*)d_in[1];
    const float* b1 = (const float*)d_in[2];
    const float* W2 = (const float*)d_in[3];
    const float* b2 = (const float*)d_in[4];
    const float* Wg = (const float*)d_in[5];
    const float* bg = (const float*)d_in[6];
    float* out = (float*)d_out;

    __half *xh, *Wgh, *W1h, *W2h, *decayh, *comb, *hidden;
    cudaGetSymbolAddress((void**)&xh, g_xh);
    cudaGetSymbolAddress((void**)&Wgh, g_Wgh);
    cudaGetSymbolAddress((void**)&W1h, g_W1h);
    cudaGetSymbolAddress((void**)&W2h, g_W2h);
    cudaGetSymbolAddress((void**)&decayh, g_decayh);
    cudaGetSymbolAddress((void**)&comb, g_comb);
    cudaGetSymbolAddress((void**)&hidden, g_hidden);

    cudaFuncSetAttribute(gemm_h<0>, cudaFuncAttributeMaxDynamicSharedMemorySize, DYN_SMEM);
    cudaFuncSetAttribute(gemm_h<1>, cudaFuncAttributeMaxDynamicSharedMemorySize, DYN_SMEM);
    cudaFuncSetAttribute(gemm_h<2>, cudaFuncAttributeMaxDynamicSharedMemorySize, DYN_SMEM);

    // 0) fp16 copies of MMA operand inputs (single launch)
    f2hall<<<F2H_TOTAL / 256, 256>>>(x, W1, W2, Wg, xh, W1h, W2h, Wgh);

    // 1) decay = sigmoid(x @ Wg^T + bg) -> fp16
    gemm_h<2><<<dim3(Id / 128, M_TOT / 128), 128, DYN_SMEM>>>(
        xh, Wgh, bg, decayh, M_TOT, Id, Id);

    // 2) fused recurrence -> combined (fp16)
    recur_fused<<<NPAIR / RPAIRS, 512>>>(xh);

    // 3+4) MLP, M-sliced for L2 residency of hidden
    for (int h = 0; h < 2; h++) {
        const size_t mo = (size_t)h * M_HALF;
        gemm_h<1><<<dim3(Hd / 128, M_HALF / 128), 128, DYN_SMEM>>>(
            comb + mo * Id, W1h, b1, hidden + mo * Hd, M_HALF, Hd, Id);
        gemm_h<0><<<dim3(Od / 128, M_HALF / 128), 128, DYN_SMEM>>>(
            hidden + mo * Hd, W2h, b2, out + mo * Od, M_HALF, Od, Hd);
    }
}